// round 5
// baseline (speedup 1.0000x reference)
#include <cuda_runtime.h>
#include <cstdint>

#define C 512
#define NBINS 256
#define RPB 8
#define LIST_CAP 512   // = C: boundary bins can never overflow -> no fallback path

// k thresholds for C=512: int(C/2), int(C*2/3), int(C*3/4), int(C*4/5)
#define K1 256u
#define K2 341u
#define K3 384u
#define K4 409u

// Monotone 32-bit key: larger float -> larger key. (Rare path only.)
__device__ __forceinline__ unsigned int mono_key(float x)
{
    unsigned int u = __float_as_uint(x);
    return u ^ (((unsigned int)((int)u >> 31)) | 0x80000000u);
}

// Descending-value bin, monotone non-increasing in x: bin 0 = largest values.
__device__ __forceinline__ int bin_of(float x)
{
    int b = __float2int_rd(fmaf(x, -32.0f, 128.0f));
    return max(0, min(255, b));
}

__global__ __launch_bounds__(32 * RPB, 5)
void multiscale_topk_kernel(const float* __restrict__ attn,
                            const float* __restrict__ w1p,
                            const float* __restrict__ w2p,
                            const float* __restrict__ w3p,
                            const float* __restrict__ w4p,
                            float* __restrict__ out)
{
    __shared__ unsigned int       hist[RPB][NBINS];
    __shared__ unsigned long long list[RPB][LIST_CAP];
    __shared__ unsigned int       listN[RPB];
    __shared__ uint4              bb[RPB];          // per k: (bin<<16) | g0
    __shared__ unsigned long long Tk[RPB][4];       // 48-bit threshold keys

    const int lane = threadIdx.x & 31;
    const int wrow = threadIdx.x >> 5;
    const int row  = blockIdx.x * RPB + wrow;
    const float* __restrict__ rp = attn + (size_t)row * C;

    // ---- init ----
    {
        uint4 z = make_uint4(0u, 0u, 0u, 0u);
        *(uint4*)&hist[wrow][lane * 8]     = z;
        *(uint4*)&hist[wrow][lane * 8 + 4] = z;
        if (lane == 0) listN[wrow] = 0u;
    }
    const float w1 = __ldg(w1p), w2 = __ldg(w2p), w3 = __ldg(w3p), w4 = __ldg(w4p);

    // ---- load 16 elems / lane (coalesced float4) ----
    float4 X[4];
    #pragma unroll
    for (int g = 0; g < 4; g++)
        X[g] = ((const float4*)rp)[lane + 32 * g];

    __syncwarp();

    // ---- histogram + pack per-element bins (1 byte each) ----
    unsigned int binw[4];
    {
        const float* xv = (const float*)X;
        #pragma unroll
        for (int g = 0; g < 4; g++) {
            unsigned int bw = 0u;
            #pragma unroll
            for (int e = 0; e < 4; e++) {
                int b = bin_of(xv[4 * g + e]);
                bw |= (unsigned int)b << (8 * e);
                atomicAdd(&hist[wrow][b], 1u);
            }
            binw[g] = bw;
        }
    }
    __syncwarp();

    // ---- scan 256 bins; locate the 4 boundary bins (G < k <= G+cnt) ----
    {
        uint4 c0 = *(uint4*)&hist[wrow][lane * 8];
        uint4 c1 = *(uint4*)&hist[wrow][lane * 8 + 4];
        unsigned int cnt[8] = {c0.x, c0.y, c0.z, c0.w, c1.x, c1.y, c1.z, c1.w};
        unsigned int pre[8], tot = 0u;
        #pragma unroll
        for (int j = 0; j < 8; j++) { pre[j] = tot; tot += cnt[j]; }
        unsigned int tt = tot;
        #pragma unroll
        for (int d = 1; d < 32; d <<= 1) {
            unsigned int v = __shfl_up_sync(0xffffffffu, tt, d);
            if (lane >= d) tt += v;
        }
        unsigned int excl = tt - tot;
        #pragma unroll
        for (int j = 0; j < 8; j++) {
            unsigned int G = excl + pre[j], E = G + cnt[j];
            if (G < K4 && E >= K1) {
                unsigned int w = ((unsigned int)(lane * 8 + j) << 16) | G;
                if (G < K1 && E >= K1) bb[wrow].x = w;
                if (G < K2 && E >= K2) bb[wrow].y = w;
                if (G < K3 && E >= K3) bb[wrow].z = w;
                if (G < K4 && E >= K4) bb[wrow].w = w;
            }
        }
    }
    __syncwarp();

    const uint4 B = bb[wrow];
    const unsigned int b1 = B.x >> 16, b2 = B.y >> 16, b3 = B.z >> 16, b4 = B.w >> 16;
    const unsigned int g1 = B.x & 0xFFFFu, g2 = B.y & 0xFFFFu,
                       g3 = B.z & 0xFFFFu, g4 = B.w & 0xFFFFu;

    // ---- gather boundary-bin candidates; remember which elems are ambiguous ----
    unsigned int ambmask = 0u;
    {
        const float* xv = (const float*)X;
        #pragma unroll
        for (int i = 0; i < 16; i++) {
            unsigned int bin = __byte_perm(binw[i >> 2], 0u, 0x7770u | (unsigned)(i & 3));
            if (bin == b1 || bin == b2 || bin == b3 || bin == b4) {
                ambmask |= 1u << i;
                int gidx = 4 * lane + 128 * (i >> 2) + (i & 3);
                unsigned long long key = ((unsigned long long)bin << 48)
                    | ((unsigned long long)mono_key(xv[i]) << 16)
                    | (unsigned long long)(65535u - (unsigned int)gidx);
                unsigned int pos = atomicAdd(&listN[wrow], 1u);
                list[wrow][pos] = key;          // pos < C always
            }
        }
    }
    __syncwarp();

    // ---- select the 4 threshold keys (k-th largest overall) ----
    {
        const unsigned int M = listN[wrow];
        for (unsigned int j = lane; j < M; j += 32) {
            unsigned long long cj = list[wrow][j];
            unsigned int binj = (unsigned int)(cj >> 48);
            unsigned int g0 = (binj == b1) ? g1 : (binj == b2) ? g2
                            : (binj == b3) ? g3 : g4;
            unsigned int r = g0;
            for (unsigned int q = 0u; q < M; q++) {
                unsigned long long cq = list[wrow][q];
                r += (unsigned int)((cq > cj) && ((cq >> 48) == binj));
            }
            unsigned long long k48 = cj & 0xFFFFFFFFFFFFull;
            if (binj == b1 && r == K1 - 1u) Tk[wrow][0] = k48;
            if (binj == b2 && r == K2 - 1u) Tk[wrow][1] = k48;
            if (binj == b3 && r == K3 - 1u) Tk[wrow][2] = k48;
            if (binj == b4 && r == K4 - 1u) Tk[wrow][3] = k48;
        }
    }
    __syncwarp();

    // ---- membership: bin compares (fast path), key vs Tk for boundary elems ----
    float s1 = 0.f, s2 = 0.f, s3 = 0.f, s4 = 0.f;
    unsigned int m1 = 0u, m2 = 0u, m3 = 0u, m4 = 0u;
    {
        float* xv = (float*)X;
        #pragma unroll
        for (int i = 0; i < 16; i++) {
            float x = xv[i];
            unsigned int bin = __byte_perm(binw[i >> 2], 0u, 0x7770u | (unsigned)(i & 3));
            bool in1, in2, in3, in4;
            if (!((ambmask >> i) & 1u)) {
                in1 = bin < b1; in2 = bin < b2; in3 = bin < b3; in4 = bin < b4;
            } else {
                int gidx = 4 * lane + 128 * (i >> 2) + (i & 3);
                unsigned long long ek = ((unsigned long long)mono_key(x) << 16)
                                      | (unsigned long long)(65535u - (unsigned int)gidx);
                in1 = ek >= Tk[wrow][0]; in2 = ek >= Tk[wrow][1];
                in3 = ek >= Tk[wrow][2]; in4 = ek >= Tk[wrow][3];
            }
            float e = __expf(x);              // softmax is shift-invariant; x is O(5)
            xv[i] = e;                        // X now holds exp values
            if (in1) { s1 += e; m1 |= 1u << i; }
            if (in2) { s2 += e; m2 |= 1u << i; }
            if (in3) { s3 += e; m3 |= 1u << i; }
            if (in4) { s4 += e; m4 |= 1u << i; }
        }
        #pragma unroll
        for (int o = 16; o > 0; o >>= 1) {
            s1 += __shfl_xor_sync(0xffffffffu, s1, o);
            s2 += __shfl_xor_sync(0xffffffffu, s2, o);
            s3 += __shfl_xor_sync(0xffffffffu, s3, o);
            s4 += __shfl_xor_sync(0xffffffffu, s4, o);
        }
    }
    const float q1 = __fdividef(w1, s1), q2 = __fdividef(w2, s2),
                q3 = __fdividef(w3, s3), q4 = __fdividef(w4, s4);

    // ---- write ----
    {
        const float* ev = (const float*)X;
        float4* op = (float4*)(out + (size_t)row * C);
        #pragma unroll
        for (int g = 0; g < 4; g++) {
            float4 o4;
            float* o = (float*)&o4;
            #pragma unroll
            for (int e = 0; e < 4; e++) {
                int i = 4 * g + e;
                float coef = 0.f;
                if ((m1 >> i) & 1u) coef += q1;
                if ((m2 >> i) & 1u) coef += q2;
                if ((m3 >> i) & 1u) coef += q3;
                if ((m4 >> i) & 1u) coef += q4;
                o[e] = ev[i] * coef;
            }
            op[lane + 32 * g] = o4;
        }
    }
}

extern "C" void kernel_launch(void* const* d_in, const int* in_sizes, int n_in,
                              void* d_out, int out_size)
{
    const float* attn = (const float*)d_in[0];
    const float* w1   = (const float*)d_in[1];
    const float* w2   = (const float*)d_in[2];
    const float* w3   = (const float*)d_in[3];
    const float* w4   = (const float*)d_in[4];
    float* out = (float*)d_out;

    int rows   = in_sizes[0] / C;
    int blocks = rows / RPB;
    multiscale_topk_kernel<<<blocks, 32 * RPB>>>(attn, w1, w2, w3, w4, out);
}

// round 6
// speedup vs baseline: 1.3534x; 1.3534x over previous
#include <cuda_runtime.h>
#include <cstdint>

#define C 512
#define NBINS 256
#define RPB 8
#define LIST_CAP 512   // = C: can never overflow -> no fallback path needed

// k thresholds for C=512: int(C/2), int(C*2/3), int(C*3/4), int(C*4/5)
#define K1 256u
#define K2 341u
#define K3 384u
#define K4 409u

// Monotone 32-bit key: larger float -> larger key. (Boundary elems only.)
__device__ __forceinline__ unsigned int mono_key(float x)
{
    unsigned int u = __float_as_uint(x);
    return u ^ (((unsigned int)((int)u >> 31)) | 0x80000000u);
}

// Descending-value bin, monotone non-increasing in x: bin 0 = largest values.
__device__ __forceinline__ int bin_of(float x)
{
    int b = __float2int_rd(fmaf(x, -32.0f, 128.0f));
    return max(0, min(255, b));
}

__global__ __launch_bounds__(32 * RPB, 4)
void multiscale_topk_kernel(const float* __restrict__ attn,
                            const float* __restrict__ w1p,
                            const float* __restrict__ w2p,
                            const float* __restrict__ w3p,
                            const float* __restrict__ w4p,
                            float* __restrict__ out)
{
    __shared__ unsigned int       hist[RPB][NBINS];
    __shared__ unsigned long long list[RPB][LIST_CAP];
    __shared__ unsigned int       listN[RPB];
    __shared__ uint4              bb[RPB];          // per k: (bin<<16) | g0
    __shared__ unsigned long long Tk[RPB][4];       // 48-bit threshold keys

    const int lane = threadIdx.x & 31;
    const int wrow = threadIdx.x >> 5;
    const int row  = blockIdx.x * RPB + wrow;
    const float* __restrict__ rp = attn + (size_t)row * C;

    // ---- init ----
    {
        uint4 z = make_uint4(0u, 0u, 0u, 0u);
        *(uint4*)&hist[wrow][lane * 8]     = z;
        *(uint4*)&hist[wrow][lane * 8 + 4] = z;
        if (lane == 0) listN[wrow] = 0u;
    }
    const float w1 = __ldg(w1p), w2 = __ldg(w2p), w3 = __ldg(w3p), w4 = __ldg(w4p);

    // ---- load 16 elems / lane (coalesced float4) ----
    float4 X[4];
    #pragma unroll
    for (int g = 0; g < 4; g++)
        X[g] = ((const float4*)rp)[lane + 32 * g];

    __syncwarp();

    // ---- histogram + pack per-element bins (1 byte each) ----
    unsigned int binw[4];
    {
        const float* xv = (const float*)X;
        #pragma unroll
        for (int g = 0; g < 4; g++) {
            unsigned int bw = 0u;
            #pragma unroll
            for (int e = 0; e < 4; e++) {
                int b = bin_of(xv[4 * g + e]);
                bw |= (unsigned int)b << (8 * e);
                atomicAdd(&hist[wrow][b], 1u);
            }
            binw[g] = bw;
        }
    }
    __syncwarp();

    // ---- scan 256 bins; locate the 4 boundary bins (G < k <= G+cnt) ----
    {
        uint4 c0 = *(uint4*)&hist[wrow][lane * 8];
        uint4 c1 = *(uint4*)&hist[wrow][lane * 8 + 4];
        unsigned int cnt[8] = {c0.x, c0.y, c0.z, c0.w, c1.x, c1.y, c1.z, c1.w};
        unsigned int pre[8], tot = 0u;
        #pragma unroll
        for (int j = 0; j < 8; j++) { pre[j] = tot; tot += cnt[j]; }
        unsigned int tt = tot;
        #pragma unroll
        for (int d = 1; d < 32; d <<= 1) {
            unsigned int v = __shfl_up_sync(0xffffffffu, tt, d);
            if (lane >= d) tt += v;
        }
        unsigned int excl = tt - tot;
        #pragma unroll
        for (int j = 0; j < 8; j++) {
            unsigned int G = excl + pre[j], E = G + cnt[j];
            if (G < K4 && E >= K1) {
                unsigned int w = ((unsigned int)(lane * 8 + j) << 16) | G;
                if (G < K1 && E >= K1) bb[wrow].x = w;
                if (G < K2 && E >= K2) bb[wrow].y = w;
                if (G < K3 && E >= K3) bb[wrow].z = w;
                if (G < K4 && E >= K4) bb[wrow].w = w;
            }
        }
    }
    __syncwarp();

    const uint4 B = bb[wrow];
    const unsigned int b1 = B.x >> 16, b2 = B.y >> 16, b3 = B.z >> 16, b4 = B.w >> 16;
    const unsigned int g1 = B.x & 0xFFFFu, g2 = B.y & 0xFFFFu,
                       g3 = B.z & 0xFFFFu, g4 = B.w & 0xFFFFu;

    // ---- fused pass: fast membership (bin < b_k), sums, masks, exp,
    //      and boundary-candidate gather (bin == some b_k) ----
    float s1 = 0.f, s2 = 0.f, s3 = 0.f, s4 = 0.f;
    unsigned int m1 = 0u, m2 = 0u, m3 = 0u, m4 = 0u;
    unsigned int ambmask = 0u;
    {
        float* xv = (float*)X;
        #pragma unroll
        for (int i = 0; i < 16; i++) {
            float x = xv[i];
            unsigned int bin = __byte_perm(binw[i >> 2], 0u, 0x7770u | (unsigned)(i & 3));
            float e = __expf(x);              // softmax is shift-invariant; |x| ~ 5
            xv[i] = e;                        // X now holds exp values
            if (bin < b1) { s1 += e; m1 |= 1u << i; }
            if (bin < b2) { s2 += e; m2 |= 1u << i; }
            if (bin < b3) { s3 += e; m3 |= 1u << i; }
            if (bin < b4) { s4 += e; m4 |= 1u << i; }
            if (bin == b1 || bin == b2 || bin == b3 || bin == b4) {
                ambmask |= 1u << i;
                int gidx = 4 * lane + 128 * (i >> 2) + (i & 3);
                unsigned long long key = ((unsigned long long)bin << 48)
                    | ((unsigned long long)mono_key(x) << 16)
                    | (unsigned long long)(65535u - (unsigned int)gidx);
                unsigned int pos = atomicAdd(&listN[wrow], 1u);
                list[wrow][pos] = key;        // pos < C always
            }
        }
    }
    __syncwarp();

    // ---- select the 4 threshold keys (k-th largest overall) ----
    {
        const unsigned int M = listN[wrow];
        for (unsigned int j = lane; j < M; j += 32) {
            unsigned long long cj = list[wrow][j];
            unsigned int binj = (unsigned int)(cj >> 48);
            unsigned int g0 = (binj == b1) ? g1 : (binj == b2) ? g2
                            : (binj == b3) ? g3 : g4;
            unsigned int r = g0;
            for (unsigned int q = 0u; q < M; q++) {
                unsigned long long cq = list[wrow][q];
                r += (unsigned int)((cq > cj) && ((cq >> 48) == binj));
            }
            unsigned long long k48 = cj & 0xFFFFFFFFFFFFull;
            if (binj == b1 && r == K1 - 1u) Tk[wrow][0] = k48;
            if (binj == b2 && r == K2 - 1u) Tk[wrow][1] = k48;
            if (binj == b3 && r == K3 - 1u) Tk[wrow][2] = k48;
            if (binj == b4 && r == K4 - 1u) Tk[wrow][3] = k48;
        }
    }
    __syncwarp();

    // ---- correction: boundary elements (~1/lane). Fast path said "out"
    //      whenever bin == b_k, so corrections are add-only. ----
    if (ambmask) {
        const float* ev = (const float*)X;
        unsigned long long TT1 = Tk[wrow][0], TT2 = Tk[wrow][1],
                           TT3 = Tk[wrow][2], TT4 = Tk[wrow][3];
        unsigned int am = ambmask;
        while (am) {
            int i = __ffs(am) - 1; am &= am - 1;
            unsigned int bin = __byte_perm(binw[i >> 2], 0u, 0x7770u | (unsigned)(i & 3));
            int gidx = 4 * lane + 128 * (i >> 2) + (i & 3);
            // reconstruct key from stored exp? need original x's key: recompute from bin+e?
            // e = exp(x) is strictly monotone in x, but we kept x's key cheaply:
            unsigned long long ek = ((unsigned long long)bin << 48)
                | ((unsigned long long)mono_key(__logf(ev[i])) << 16)
                | (unsigned long long)(65535u - (unsigned int)gidx);
            // NOTE: log(exp(x)) != x bitwise; must not rely on it. Instead reload x.
            float x = rp[gidx];
            ek = ((unsigned long long)bin << 48)
               | ((unsigned long long)mono_key(x) << 16)
               | (unsigned long long)(65535u - (unsigned int)gidx);
            float e = ev[i];
            if (bin == b1 && ek >= (((unsigned long long)b1 << 48) | TT1)) { s1 += e; m1 |= 1u << i; }
            if (bin == b2 && ek >= (((unsigned long long)b2 << 48) | TT2)) { s2 += e; m2 |= 1u << i; }
            if (bin == b3 && ek >= (((unsigned long long)b3 << 48) | TT3)) { s3 += e; m3 |= 1u << i; }
            if (bin == b4 && ek >= (((unsigned long long)b4 << 48) | TT4)) { s4 += e; m4 |= 1u << i; }
        }
    }

    // ---- reduce sums, coefficients ----
    #pragma unroll
    for (int o = 16; o > 0; o >>= 1) {
        s1 += __shfl_xor_sync(0xffffffffu, s1, o);
        s2 += __shfl_xor_sync(0xffffffffu, s2, o);
        s3 += __shfl_xor_sync(0xffffffffu, s3, o);
        s4 += __shfl_xor_sync(0xffffffffu, s4, o);
    }
    const float q1 = __fdividef(w1, s1), q2 = __fdividef(w2, s2),
                q3 = __fdividef(w3, s3), q4 = __fdividef(w4, s4);

    // ---- write ----
    {
        const float* ev = (const float*)X;
        float4* op = (float4*)(out + (size_t)row * C);
        #pragma unroll
        for (int g = 0; g < 4; g++) {
            float4 o4;
            float* o = (float*)&o4;
            #pragma unroll
            for (int e = 0; e < 4; e++) {
                int i = 4 * g + e;
                float coef = 0.f;
                if ((m1 >> i) & 1u) coef += q1;
                if ((m2 >> i) & 1u) coef += q2;
                if ((m3 >> i) & 1u) coef += q3;
                if ((m4 >> i) & 1u) coef += q4;
                o[e] = ev[i] * coef;
            }
            op[lane + 32 * g] = o4;
        }
    }
}

extern "C" void kernel_launch(void* const* d_in, const int* in_sizes, int n_in,
                              void* d_out, int out_size)
{
    const float* attn = (const float*)d_in[0];
    const float* w1   = (const float*)d_in[1];
    const float* w2   = (const float*)d_in[2];
    const float* w3   = (const float*)d_in[3];
    const float* w4   = (const float*)d_in[4];
    float* out = (float*)d_out;

    int rows   = in_sizes[0] / C;
    int blocks = rows / RPB;
    multiscale_topk_kernel<<<blocks, 32 * RPB>>>(attn, w1, w2, w3, w4, out);
}